// round 8
// baseline (speedup 1.0000x reference)
#include <cuda_runtime.h>
#include <cstdint>
#include <cstddef>

// Problem constants (static in reference)
constexpr int Mm = 512, Nn = 4096, Kdim = 4096, Dd = 128, Hh = 32, Ll = 4096, Pp = 3584;
constexpr size_t OUT0 = (size_t)Mm * Nn;

// Scratch (device globals: allocation-free per harness rules)
__device__ float g_q [(size_t)Hh * Mm * Dd];   // 8 MB [H][M][D]
__device__ float g_Kn[(size_t)Hh * Mm * Dd];   // 8 MB new K rows [H][M][D]
__device__ float g_Vn[(size_t)Hh * Mm * Dd];   // 8 MB new V rows [H][M][D]
__device__ float g_S [(size_t)Hh * Mm * Ll];   // 256 MB raw scores [H*M][L]
__device__ float g_invs[Hh * Mm];              // 1/sum(exp(s)) per row

// ---------------------------------------------------------------------------
// TF32 helpers (baseline PTX only — no sm_103a-suffixed features)
// ---------------------------------------------------------------------------
__device__ __forceinline__ void tf32split(float f, uint32_t& hi, uint32_t& lo) {
    asm("cvt.rna.tf32.f32 %0, %1;" : "=r"(hi) : "f"(f));
    float r = f - __uint_as_float(hi);
    asm("cvt.rna.tf32.f32 %0, %1;" : "=r"(lo) : "f"(r));
}

__device__ __forceinline__ void mma8(float* c, const uint32_t* a, const uint32_t* b) {
    asm("mma.sync.aligned.m16n8k8.row.col.f32.tf32.tf32.f32 "
        "{%0,%1,%2,%3}, {%4,%5,%6,%7}, {%8,%9}, {%0,%1,%2,%3};"
        : "+f"(c[0]), "+f"(c[1]), "+f"(c[2]), "+f"(c[3])
        : "r"(a[0]), "r"(a[1]), "r"(a[2]), "r"(a[3]), "r"(b[0]), "r"(b[1]));
}

// ---------------------------------------------------------------------------
// SMEM layout (uint32 words), per buffer:
//   Ahi [128][A_STR] , Alo, Bhi [16][B_STR], Blo.  Double buffered.
// Pre-split tf32 hi/lo => inner loop is pure LDS + MMA (no ALU).
// A_STR=20: frag bank (20g+t4)&31 distinct.  B_STR=140: (12t4+g)&31 distinct.
// ---------------------------------------------------------------------------
#define A_STR 20
#define B_STR 140
#define AH_O 0
#define AL_O (128 * A_STR)            // 2560
#define BH_O (2 * 128 * A_STR)        // 5120
#define BL_O (BH_O + 16 * B_STR)      // 7360
#define BUF_W (BL_O + 16 * B_STR)     // 9600
constexpr int SMEMSZ = 2 * BUF_W * 4; // 76800 B

// B rows come from two sources split at row `split` (cache vs freshly-projected)
struct BSrc { const float* p0; const float* p1; int split; size_t ld; };
__device__ __forceinline__ const float* brow(const BSrc& s, int r) {
    return (r < s.split) ? s.p0 + (size_t)r * s.ld : s.p1 + (size_t)(r - s.split) * s.ld;
}

struct F8 { float v[8]; };

template <bool EXPA>
__device__ __forceinline__ F8 fetchA(const float* __restrict__ A, size_t lda,
                                     int am0, int kb, int tid) {
    int r = tid >> 1, kq = (tid & 1) * 8;
    const float* p = A + (size_t)(am0 + r) * lda + kb + kq;
    float4 a = *(const float4*)p, b = *(const float4*)(p + 4);
    F8 o;
    o.v[0] = a.x; o.v[1] = a.y; o.v[2] = a.z; o.v[3] = a.w;
    o.v[4] = b.x; o.v[5] = b.y; o.v[6] = b.z; o.v[7] = b.w;
    if (EXPA) {
#pragma unroll
        for (int j = 0; j < 8; j++) o.v[j] = __expf(o.v[j]);
    }
    return o;
}
__device__ __forceinline__ void stA(uint32_t* buf, const F8& o, int tid) {
    int r = tid >> 1, kq = (tid & 1) * 8;
    uint32_t h[8], l[8];
#pragma unroll
    for (int j = 0; j < 8; j++) tf32split(o.v[j], h[j], l[j]);
    uint32_t* ph = buf + AH_O + r * A_STR + kq;
    uint32_t* pl = buf + AL_O + r * A_STR + kq;
    *(uint4*)ph = make_uint4(h[0], h[1], h[2], h[3]);
    *(uint4*)(ph + 4) = make_uint4(h[4], h[5], h[6], h[7]);
    *(uint4*)pl = make_uint4(l[0], l[1], l[2], l[3]);
    *(uint4*)(pl + 4) = make_uint4(l[4], l[5], l[6], l[7]);
}

// direct B: smem[k][n] = B[k0+k][bn0+n]
__device__ __forceinline__ F8 fetchBd(const BSrc& s, int bn0, int k0, int tid) {
    int k = tid >> 4, n0 = (tid & 15) * 8;
    const float* p = brow(s, k0 + k) + bn0 + n0;
    float4 a = *(const float4*)p, b = *(const float4*)(p + 4);
    F8 o;
    o.v[0] = a.x; o.v[1] = a.y; o.v[2] = a.z; o.v[3] = a.w;
    o.v[4] = b.x; o.v[5] = b.y; o.v[6] = b.z; o.v[7] = b.w;
    return o;
}
__device__ __forceinline__ void stBd(uint32_t* buf, const F8& o, int tid) {
    int k = tid >> 4, n0 = (tid & 15) * 8;
    uint32_t h[8], l[8];
#pragma unroll
    for (int j = 0; j < 8; j++) tf32split(o.v[j], h[j], l[j]);
    uint32_t* ph = buf + BH_O + k * B_STR + n0;
    uint32_t* pl = buf + BL_O + k * B_STR + n0;
    *(uint4*)ph = make_uint4(h[0], h[1], h[2], h[3]);
    *(uint4*)(ph + 4) = make_uint4(h[4], h[5], h[6], h[7]);
    *(uint4*)pl = make_uint4(l[0], l[1], l[2], l[3]);
    *(uint4*)(pl + 4) = make_uint4(l[4], l[5], l[6], l[7]);
}

// transposed B: smem[k][n] = B[bn0+n][kb+k]  (scores: K-cache is [l][d])
__device__ __forceinline__ F8 fetchBt(const BSrc& s, int bn0, int kb, int tid) {
    int l = tid >> 1, dq = (tid & 1) * 8;
    const float* p = brow(s, bn0 + l) + kb + dq;
    float4 a = *(const float4*)p, b = *(const float4*)(p + 4);
    F8 o;
    o.v[0] = a.x; o.v[1] = a.y; o.v[2] = a.z; o.v[3] = a.w;
    o.v[4] = b.x; o.v[5] = b.y; o.v[6] = b.z; o.v[7] = b.w;
    return o;
}
__device__ __forceinline__ void stBt(uint32_t* buf, const F8& o, int tid) {
    int l = tid >> 1, dq = (tid & 1) * 8;
#pragma unroll
    for (int j = 0; j < 8; j++) {
        uint32_t h, lo;
        tf32split(o.v[j], h, lo);
        buf[BH_O + (dq + j) * B_STR + l] = h;
        buf[BL_O + (dq + j) * B_STR + l] = lo;
    }
}

// ---------------------------------------------------------------------------
// GEMM core: C[128,128] = A[128xK] * B[Kx128]
// 8 warps laid out 2M x 4N; warp tile 64x32 = 4x4 m16n8k8 tiles.
// 3xTF32, pass-major: all 16 accumulators between reuses => no RAW stall.
// ---------------------------------------------------------------------------
template <int NCHUNK, bool BTRANS, bool EXPA>
__device__ __forceinline__ void gemm_tc(const float* __restrict__ A, size_t lda, int am0,
                                        BSrc bs, int bn0,
                                        uint32_t* sm, float (&acc)[4][4][4]) {
    const int tid = threadIdx.x;
    const int lane = tid & 31, wid = tid >> 5;
    const int wm0 = (wid >> 2) * 64, wn0 = (wid & 3) * 32;
    const int g = lane >> 2, t4 = lane & 3;

#pragma unroll
    for (int i = 0; i < 4; i++)
#pragma unroll
        for (int j = 0; j < 4; j++)
#pragma unroll
            for (int q = 0; q < 4; q++) acc[i][j][q] = 0.f;

    F8 ra = fetchA<EXPA>(A, lda, am0, 0, tid);
    F8 rb = BTRANS ? fetchBt(bs, bn0, 0, tid) : fetchBd(bs, bn0, 0, tid);

#pragma unroll 1
    for (int c = 0; c < NCHUNK; c++) {
        uint32_t* buf = sm + (c & 1) * BUF_W;
        stA(buf, ra, tid);
        if (BTRANS) stBt(buf, rb, tid); else stBd(buf, rb, tid);
        __syncthreads();
        if (c + 1 < NCHUNK) {
            ra = fetchA<EXPA>(A, lda, am0, (c + 1) * 16, tid);
            rb = BTRANS ? fetchBt(bs, bn0, (c + 1) * 16, tid)
                        : fetchBd(bs, bn0, (c + 1) * 16, tid);
        }
        const uint32_t* Ah = buf + AH_O;
        const uint32_t* Al = buf + AL_O;
        const uint32_t* Bh = buf + BH_O;
        const uint32_t* Bl = buf + BL_O;
#pragma unroll
        for (int kt = 0; kt < 2; kt++) {
            const int kc = kt * 8 + t4;
            uint32_t ah[4][4], al[4][4], bh[4][2], bl[4][2];
#pragma unroll
            for (int i = 0; i < 4; i++) {
                int r0 = (wm0 + i * 16 + g) * A_STR + kc;
                ah[i][0] = Ah[r0];                 al[i][0] = Al[r0];
                ah[i][1] = Ah[r0 + 8 * A_STR];     al[i][1] = Al[r0 + 8 * A_STR];
                ah[i][2] = Ah[r0 + 4];             al[i][2] = Al[r0 + 4];
                ah[i][3] = Ah[r0 + 8 * A_STR + 4]; al[i][3] = Al[r0 + 8 * A_STR + 4];
            }
#pragma unroll
            for (int j = 0; j < 4; j++) {
                int nb = kc * B_STR + wn0 + j * 8 + g;
                bh[j][0] = Bh[nb]; bh[j][1] = Bh[nb + 4 * B_STR];
                bl[j][0] = Bl[nb]; bl[j][1] = Bl[nb + 4 * B_STR];
            }
            // pass-major: 16 independent accumulators between reuses
#pragma unroll
            for (int i = 0; i < 4; i++)
#pragma unroll
                for (int j = 0; j < 4; j++) mma8(acc[i][j], ah[i], bh[j]);
#pragma unroll
            for (int i = 0; i < 4; i++)
#pragma unroll
                for (int j = 0; j < 4; j++) mma8(acc[i][j], ah[i], bl[j]);
#pragma unroll
            for (int i = 0; i < 4; i++)
#pragma unroll
                for (int j = 0; j < 4; j++) mma8(acc[i][j], al[i], bh[j]);
        }
        __syncthreads();
    }
}

__device__ __forceinline__ void store_acc(float (&acc)[4][4][4], float* __restrict__ dst,
                                          size_t ldd, const float* __restrict__ rowscale) {
    const int tid = threadIdx.x;
    const int lane = tid & 31, wid = tid >> 5;
    const int wm0 = (wid >> 2) * 64, wn0 = (wid & 3) * 32;
    const int g = lane >> 2, t4 = lane & 3;
#pragma unroll
    for (int i = 0; i < 4; i++) {
        int r0 = wm0 + i * 16 + g;
        float s0 = rowscale ? rowscale[r0] : 1.f;
        float s1 = rowscale ? rowscale[r0 + 8] : 1.f;
#pragma unroll
        for (int j = 0; j < 4; j++) {
            int cn = wn0 + j * 8 + t4 * 2;
            *(float2*)&dst[(size_t)r0 * ldd + cn] =
                make_float2(acc[i][j][0] * s0, acc[i][j][1] * s0);
            *(float2*)&dst[(size_t)(r0 + 8) * ldd + cn] =
                make_float2(acc[i][j][2] * s1, acc[i][j][3] * s1);
        }
    }
}

// ---------------------------------------------------------------------------
// Kernels
// ---------------------------------------------------------------------------
extern __shared__ uint32_t dsm_u32[];

// QKV: C = X @ W_z, one (m-block, z, head) tile per CTA
__global__ __launch_bounds__(256, 1)
void k_qkv(const float* __restrict__ X, const float* __restrict__ Wq,
           const float* __restrict__ Wk, const float* __restrict__ Wv) {
    int z = blockIdx.x >> 5, head = blockIdx.x & 31, bm0 = blockIdx.y * 128;
    const float* W = (z == 0) ? Wq : (z == 1) ? Wk : Wv;
    BSrc bs{W, W, Kdim, (size_t)Nn};
    float acc[4][4][4];
    gemm_tc<Kdim / 16, false, false>(X, Kdim, bm0, bs, head * 128, dsm_u32, acc);
    float* dst = (z == 0) ? g_q  + ((size_t)head * Mm + bm0) * Dd
               : (z == 1) ? g_Kn + ((size_t)head * Mm + bm0) * Dd
                          : g_Vn + ((size_t)head * Mm + bm0) * Dd;
    store_acc(acc, dst, Dd, nullptr);
}

// Scores: S[h][m][l] = q[h] @ K[h]^T; K rows <P from input cache, >=P from g_Kn
__global__ __launch_bounds__(256, 1)
void k_scores(const float* __restrict__ cacheK) {
    int h = blockIdx.z, bm0 = blockIdx.y * 128, l0 = blockIdx.x * 128;
    BSrc bs{cacheK + (size_t)h * Ll * Dd, g_Kn + (size_t)h * Mm * Dd, Pp, (size_t)Dd};
    float acc[4][4][4];
    gemm_tc<Dd / 16, true, false>(g_q + (size_t)h * Mm * Dd, Dd, bm0, bs, l0, dsm_u32, acc);
    store_acc(acc, g_S + ((size_t)h * Mm + bm0) * Ll + l0, Ll, nullptr);
}

// Output: out[m, h*128+d] = (exp(S)[h] @ V[h]) * inv_sum; exp applied in A-loader
__global__ __launch_bounds__(256, 1)
void k_out(const float* __restrict__ cacheV, float* __restrict__ dout) {
    int h = blockIdx.y, bm0 = blockIdx.x * 128;
    BSrc bs{cacheV + (size_t)h * Ll * Dd, g_Vn + (size_t)h * Mm * Dd, Pp, (size_t)Dd};
    float acc[4][4][4];
    gemm_tc<Ll / 16, false, true>(g_S + (size_t)h * Mm * Ll, Ll, bm0, bs, 0, dsm_u32, acc);
    store_acc(acc, dout + (size_t)bm0 * Nn + h * Dd, Nn, g_invs + h * Mm + bm0);
}

// Dual-exp row kernel: reads raw S (no writeback), writes normalized perturb + invs.
__global__ __launch_bounds__(256)
void softmax_rows(const float* __restrict__ noise, float* __restrict__ dout) {
    const int row = blockIdx.x;  // h*Mm + m
    const float* S = g_S + (size_t)row * Ll;
    const float* nz = noise + (size_t)row * Ll;
    float* pout = dout + OUT0 + (size_t)row * Ll;
    __shared__ float ep[Ll];
    __shared__ float r1[256], r2[256];
    const int tid = threadIdx.x;

    float ss = 0.f, sp = 0.f;
    for (int l = tid; l < Ll; l += 256) {
        float s = S[l];
        ss += __expf(s);
        float e2 = __expf((s + nz[l]) * (1.0f / 1.5f));
        ep[l] = e2;
        sp += e2;
    }
    r1[tid] = ss; r2[tid] = sp;
    __syncthreads();
    for (int st = 128; st > 0; st >>= 1) {
        if (tid < st) { r1[tid] += r1[tid + st]; r2[tid] += r2[tid + st]; }
        __syncthreads();
    }
    if (tid == 0) g_invs[row] = 1.0f / r1[0];
    const float ip = 1.0f / r2[0];
    for (int l = tid; l < Ll; l += 256) pout[l] = ep[l] * ip;
}

// ---------------------------------------------------------------------------
// Launch
// ---------------------------------------------------------------------------
extern "C" void kernel_launch(void* const* d_in, const int* in_sizes, int n_in,
                              void* d_out, int out_size) {
    const float* X      = (const float*)d_in[0];
    const float* Wq     = (const float*)d_in[1];
    const float* Wk     = (const float*)d_in[2];
    const float* Wv     = (const float*)d_in[3];
    const float* noise  = (const float*)d_in[4];
    const float* cacheK = (const float*)d_in[5];
    const float* cacheV = (const float*)d_in[6];
    float* out = (float*)d_out;
    (void)in_sizes; (void)n_in; (void)out_size;   // P is static (3584)

    cudaFuncSetAttribute(k_qkv,    cudaFuncAttributeMaxDynamicSharedMemorySize, SMEMSZ);
    cudaFuncSetAttribute(k_scores, cudaFuncAttributeMaxDynamicSharedMemorySize, SMEMSZ);
    cudaFuncSetAttribute(k_out,    cudaFuncAttributeMaxDynamicSharedMemorySize, SMEMSZ);

    k_qkv<<<dim3(96, 4), 256, SMEMSZ>>>(X, Wq, Wk, Wv);
    k_scores<<<dim3(32, 4, 32), 256, SMEMSZ>>>(cacheK);
    softmax_rows<<<Hh * Mm, 256>>>(noise, out);
    k_out<<<dim3(4, 32), 256, SMEMSZ>>>(cacheV, out);
}

// round 9
// speedup vs baseline: 1.0972x; 1.0972x over previous
#include <cuda_runtime.h>
#include <cstdint>
#include <cstddef>

// Problem constants (static in reference)
constexpr int Mm = 512, Nn = 4096, Kdim = 4096, Dd = 128, Hh = 32, Ll = 4096, Pp = 3584;
constexpr size_t OUT0 = (size_t)Mm * Nn;

// Scratch (device globals: allocation-free per harness rules)
__device__ float g_q [(size_t)Hh * Mm * Dd];   // 8 MB [H][M][D]
__device__ float g_Kn[(size_t)Hh * Mm * Dd];   // 8 MB new K rows [H][M][D]
__device__ float g_Vn[(size_t)Hh * Mm * Dd];   // 8 MB new V rows [H][M][D]
__device__ float g_S [(size_t)Hh * Mm * Ll];   // 256 MB raw scores [H*M][L]
__device__ float g_invs[Hh * Mm];              // 1/sum(exp(s)) per row

// ---------------------------------------------------------------------------
// PTX helpers (all baseline, no sm_103a-suffixed features)
// ---------------------------------------------------------------------------
__device__ __forceinline__ uint32_t smem_u32(const void* p) {
    uint32_t a;
    asm("{ .reg .u64 t; cvta.to.shared.u64 t, %1; cvt.u32.u64 %0, t; }" : "=r"(a) : "l"(p));
    return a;
}
__device__ __forceinline__ void tf32split(float f, uint32_t& hi, uint32_t& lo) {
    asm("cvt.rna.tf32.f32 %0, %1;" : "=r"(hi) : "f"(f));
    float r = f - __uint_as_float(hi);
    asm("cvt.rna.tf32.f32 %0, %1;" : "=r"(lo) : "f"(r));
}
__device__ __forceinline__ void mma8(float* c, const uint32_t* a, const uint32_t* b) {
    asm("mma.sync.aligned.m16n8k8.row.col.f32.tf32.tf32.f32 "
        "{%0,%1,%2,%3}, {%4,%5,%6,%7}, {%8,%9}, {%0,%1,%2,%3};"
        : "+f"(c[0]), "+f"(c[1]), "+f"(c[2]), "+f"(c[3])
        : "r"(a[0]), "r"(a[1]), "r"(a[2]), "r"(a[3]), "r"(b[0]), "r"(b[1]));
}
__device__ __forceinline__ void ldsm4(uint32_t& r0, uint32_t& r1, uint32_t& r2, uint32_t& r3,
                                      uint32_t addr) {
    asm volatile("ldmatrix.sync.aligned.m8n8.x4.shared.b16 {%0,%1,%2,%3}, [%4];"
                 : "=r"(r0), "=r"(r1), "=r"(r2), "=r"(r3) : "r"(addr));
}
__device__ __forceinline__ void cpasync16(uint32_t dst, const float* src) {
    asm volatile("cp.async.cg.shared.global [%0], [%1], 16;" :: "r"(dst), "l"(src));
}
#define CP_COMMIT() asm volatile("cp.async.commit_group;" ::: "memory")
#define CP_WAIT1()  asm volatile("cp.async.wait_group 1;" ::: "memory")

// ---------------------------------------------------------------------------
// SMEM: 3 pipeline stages. Stage = A[128][20] fp32 + B (2560 words either
// [128][20] K-major or [16][140] n-major, padded). STAGE_W = 5120 words.
// A/B K-major rows are 80B: LDSM row-segments cover all 32 banks (no conflict).
// B n-major stride 140: scalar frag bank (12*t4+g)&31, all distinct.
// ---------------------------------------------------------------------------
#define A_STR 20
#define B_STR 140
#define STAGE_W 5120
#define B_OFF_W 2560
constexpr int SMEMSZ = 3 * STAGE_W * 4;   // 61440 B

// B rows come from two sources split at row `split` (cache vs freshly-projected)
struct BSrc { const float* p0; const float* p1; int split; size_t ld; };
__device__ __forceinline__ const float* brow(const BSrc& s, int r) {
    return (r < s.split) ? s.p0 + (size_t)r * s.ld : s.p1 + (size_t)(r - s.split) * s.ld;
}

// Issue one stage of cp.async (A tile [128][16] + B tile)
template <bool BKMAJOR>
__device__ __forceinline__ void issue_stage(uint32_t sb, const float* __restrict__ A,
                                            size_t lda, int am0, const BSrc& bs, int bn0,
                                            int kb, int tid) {
    {   // A: thread pair per row
        int r = tid >> 1, kq = (tid & 1) * 8;
        const float* src = A + (size_t)(am0 + r) * lda + kb + kq;
        uint32_t dst = sb + (r * A_STR + kq) * 4;
        cpasync16(dst, src); cpasync16(dst + 16, src + 4);
    }
    if (BKMAJOR) {   // B K-major: same pattern, rows = n
        int n = tid >> 1, kq = (tid & 1) * 8;
        const float* src = brow(bs, bn0 + n) + kb + kq;
        uint32_t dst = sb + B_OFF_W * 4 + (n * A_STR + kq) * 4;
        cpasync16(dst, src); cpasync16(dst + 16, src + 4);
    } else {         // B n-major: [k][n]
        int k = tid >> 4, n0 = (tid & 15) * 8;
        const float* src = brow(bs, kb + k) + bn0 + n0;
        uint32_t dst = sb + B_OFF_W * 4 + (k * B_STR + n0) * 4;
        cpasync16(dst, src); cpasync16(dst + 16, src + 4);
    }
}

// ---------------------------------------------------------------------------
// GEMM core: C[128,128] = A[128xK] * B[Kx128]
// 8 warps 2M x 4N; warp tile 64x32 = 4x4 m16n8k8 tiles.
// Raw fp32 smem; LDSM fragments; tf32 split (+ optional exp on A) in registers.
// 3xTF32 passes, pass-major.
// ---------------------------------------------------------------------------
template <int NCHUNK, bool BKMAJOR, bool EXPA>
__device__ __forceinline__ void gemm_tc(const float* __restrict__ A, size_t lda, int am0,
                                        BSrc bs, int bn0,
                                        uint32_t* sm, float (&acc)[4][4][4]) {
    const int tid = threadIdx.x;
    const int lane = tid & 31, wid = tid >> 5;
    const int wm0 = (wid >> 2) * 64, wn0 = (wid & 3) * 32;
    const int g = lane >> 2, t4 = lane & 3;
    const uint32_t sbase = smem_u32(sm);

#pragma unroll
    for (int i = 0; i < 4; i++)
#pragma unroll
        for (int j = 0; j < 4; j++)
#pragma unroll
            for (int q = 0; q < 4; q++) acc[i][j][q] = 0.f;

    issue_stage<BKMAJOR>(sbase, A, lda, am0, bs, bn0, 0, tid);
    CP_COMMIT();
    issue_stage<BKMAJOR>(sbase + STAGE_W * 4, A, lda, am0, bs, bn0, 16, tid);
    CP_COMMIT();

    // ldmatrix address components (constant per thread)
    const uint32_t a_row = wm0 + (lane & 15);
    const uint32_t a_col = ((lane >> 4) << 2);
    const uint32_t b_row = wn0 + (lane & 7) + ((lane & 16) ? 8 : 0);
    const uint32_t b_col = ((lane & 8) ? 4 : 0);

#pragma unroll 1
    for (int c = 0; c < NCHUNK; c++) {
        CP_WAIT1();
        __syncthreads();
        if (c + 2 < NCHUNK)
            issue_stage<BKMAJOR>(sbase + ((c + 2) % 3) * STAGE_W * 4,
                                 A, lda, am0, bs, bn0, (c + 2) * 16, tid);
        CP_COMMIT();

        const uint32_t aB = sbase + (c % 3) * STAGE_W * 4;
        const uint32_t bB = aB + B_OFF_W * 4;
        const uint32_t* Bs = (const uint32_t*)sm + (c % 3) * STAGE_W + B_OFF_W;

#pragma unroll
        for (int kt = 0; kt < 2; kt++) {
            // ---- A fragments (LDSM) ----
            uint32_t araw[4][4];
#pragma unroll
            for (int i = 0; i < 4; i++)
                ldsm4(araw[i][0], araw[i][1], araw[i][2], araw[i][3],
                      aB + ((a_row + i * 16) * A_STR + kt * 8 + a_col) * 4);
            // ---- B fragments ----
            uint32_t bh[4][2], bl[4][2];
            if (BKMAJOR) {
                uint32_t braw[4][2];
#pragma unroll
                for (int jp = 0; jp < 2; jp++) {
                    uint32_t r0, r1, r2, r3;
                    ldsm4(r0, r1, r2, r3,
                          bB + ((b_row + jp * 16) * A_STR + kt * 8 + b_col) * 4);
                    braw[jp * 2][0] = r0;     braw[jp * 2][1] = r1;
                    braw[jp * 2 + 1][0] = r2; braw[jp * 2 + 1][1] = r3;
                }
#pragma unroll
                for (int j = 0; j < 4; j++)
#pragma unroll
                    for (int q = 0; q < 2; q++)
                        tf32split(__uint_as_float(braw[j][q]), bh[j][q], bl[j][q]);
            } else {
                const int kc = kt * 8 + t4;
#pragma unroll
                for (int j = 0; j < 4; j++) {
                    float f0 = __uint_as_float(Bs[kc * B_STR + wn0 + j * 8 + g]);
                    float f1 = __uint_as_float(Bs[(kc + 4) * B_STR + wn0 + j * 8 + g]);
                    tf32split(f0, bh[j][0], bl[j][0]);
                    tf32split(f1, bh[j][1], bl[j][1]);
                }
            }
            // ---- A split (+exp) ----
            uint32_t ah[4][4], al[4][4];
#pragma unroll
            for (int i = 0; i < 4; i++)
#pragma unroll
                for (int q = 0; q < 4; q++) {
                    float f = __uint_as_float(araw[i][q]);
                    if (EXPA) f = __expf(f);
                    tf32split(f, ah[i][q], al[i][q]);
                }
            // ---- MMAs, pass-major (16 independent accs between reuses) ----
#pragma unroll
            for (int i = 0; i < 4; i++)
#pragma unroll
                for (int j = 0; j < 4; j++) mma8(acc[i][j], ah[i], bh[j]);
#pragma unroll
            for (int i = 0; i < 4; i++)
#pragma unroll
                for (int j = 0; j < 4; j++) mma8(acc[i][j], ah[i], bl[j]);
#pragma unroll
            for (int i = 0; i < 4; i++)
#pragma unroll
                for (int j = 0; j < 4; j++) mma8(acc[i][j], al[i], bh[j]);
        }
        __syncthreads();
    }
}

__device__ __forceinline__ void store_acc(float (&acc)[4][4][4], float* __restrict__ dst,
                                          size_t ldd, const float* __restrict__ rowscale) {
    const int tid = threadIdx.x;
    const int lane = tid & 31, wid = tid >> 5;
    const int wm0 = (wid >> 2) * 64, wn0 = (wid & 3) * 32;
    const int g = lane >> 2, t4 = lane & 3;
#pragma unroll
    for (int i = 0; i < 4; i++) {
        int r0 = wm0 + i * 16 + g;
        float s0 = rowscale ? rowscale[r0] : 1.f;
        float s1 = rowscale ? rowscale[r0 + 8] : 1.f;
#pragma unroll
        for (int j = 0; j < 4; j++) {
            int cn = wn0 + j * 8 + t4 * 2;
            *(float2*)&dst[(size_t)r0 * ldd + cn] =
                make_float2(acc[i][j][0] * s0, acc[i][j][1] * s0);
            *(float2*)&dst[(size_t)(r0 + 8) * ldd + cn] =
                make_float2(acc[i][j][2] * s1, acc[i][j][3] * s1);
        }
    }
}

// ---------------------------------------------------------------------------
// Kernels
// ---------------------------------------------------------------------------
extern __shared__ uint32_t dsm_u32[];

// QKV: C = X @ W_z; W is [k][n] -> B n-major
__global__ __launch_bounds__(256, 1)
void k_qkv(const float* __restrict__ X, const float* __restrict__ Wq,
           const float* __restrict__ Wk, const float* __restrict__ Wv) {
    int z = blockIdx.x >> 5, head = blockIdx.x & 31, bm0 = blockIdx.y * 128;
    const float* W = (z == 0) ? Wq : (z == 1) ? Wk : Wv;
    BSrc bs{W, W, Kdim, (size_t)Nn};
    float acc[4][4][4];
    gemm_tc<Kdim / 16, false, false>(X, Kdim, bm0, bs, head * 128, dsm_u32, acc);
    float* dst = (z == 0) ? g_q  + ((size_t)head * Mm + bm0) * Dd
               : (z == 1) ? g_Kn + ((size_t)head * Mm + bm0) * Dd
                          : g_Vn + ((size_t)head * Mm + bm0) * Dd;
    store_acc(acc, dst, Dd, nullptr);
}

// Scores: S = q @ K^T; K-cache is [l][d] (K-major) -> B K-major, LDSM both sides
__global__ __launch_bounds__(256, 1)
void k_scores(const float* __restrict__ cacheK) {
    int h = blockIdx.z, bm0 = blockIdx.y * 128, l0 = blockIdx.x * 128;
    BSrc bs{cacheK + (size_t)h * Ll * Dd, g_Kn + (size_t)h * Mm * Dd, Pp, (size_t)Dd};
    float acc[4][4][4];
    gemm_tc<Dd / 16, true, false>(g_q + (size_t)h * Mm * Dd, Dd, bm0, bs, l0, dsm_u32, acc);
    store_acc(acc, g_S + ((size_t)h * Mm + bm0) * Ll + l0, Ll, nullptr);
}

// Output: out = (exp(S) @ V) * inv_sum; V is [l][d] -> B n-major; exp in-register
__global__ __launch_bounds__(256, 1)
void k_out(const float* __restrict__ cacheV, float* __restrict__ dout) {
    int h = blockIdx.y, bm0 = blockIdx.x * 128;
    BSrc bs{cacheV + (size_t)h * Ll * Dd, g_Vn + (size_t)h * Mm * Dd, Pp, (size_t)Dd};
    float acc[4][4][4];
    gemm_tc<Ll / 16, false, true>(g_S + (size_t)h * Mm * Ll, Ll, bm0, bs, 0, dsm_u32, acc);
    store_acc(acc, dout + (size_t)bm0 * Nn + h * Dd, Nn, g_invs + h * Mm + bm0);
}

// Dual-exp row kernel: reads raw S, writes normalized perturb + invs.
__global__ __launch_bounds__(256)
void softmax_rows(const float* __restrict__ noise, float* __restrict__ dout) {
    const int row = blockIdx.x;  // h*Mm + m
    const float* S = g_S + (size_t)row * Ll;
    const float* nz = noise + (size_t)row * Ll;
    float* pout = dout + OUT0 + (size_t)row * Ll;
    __shared__ float ep[Ll];
    __shared__ float r1[256], r2[256];
    const int tid = threadIdx.x;

    float ss = 0.f, sp = 0.f;
    for (int l = tid; l < Ll; l += 256) {
        float s = S[l];
        ss += __expf(s);
        float e2 = __expf((s + nz[l]) * (1.0f / 1.5f));
        ep[l] = e2;
        sp += e2;
    }
    r1[tid] = ss; r2[tid] = sp;
    __syncthreads();
    for (int st = 128; st > 0; st >>= 1) {
        if (tid < st) { r1[tid] += r1[tid + st]; r2[tid] += r2[tid + st]; }
        __syncthreads();
    }
    if (tid == 0) g_invs[row] = 1.0f / r1[0];
    const float ip = 1.0f / r2[0];
    for (int l = tid; l < Ll; l += 256) pout[l] = ep[l] * ip;
}

// ---------------------------------------------------------------------------
// Launch
// ---------------------------------------------------------------------------
extern "C" void kernel_launch(void* const* d_in, const int* in_sizes, int n_in,
                              void* d_out, int out_size) {
    const float* X      = (const float*)d_in[0];
    const float* Wq     = (const float*)d_in[1];
    const float* Wk     = (const float*)d_in[2];
    const float* Wv     = (const float*)d_in[3];
    const float* noise  = (const float*)d_in[4];
    const float* cacheK = (const float*)d_in[5];
    const float* cacheV = (const float*)d_in[6];
    float* out = (float*)d_out;
    (void)in_sizes; (void)n_in; (void)out_size;   // P is static (3584)

    cudaFuncSetAttribute(k_qkv,    cudaFuncAttributeMaxDynamicSharedMemorySize, SMEMSZ);
    cudaFuncSetAttribute(k_scores, cudaFuncAttributeMaxDynamicSharedMemorySize, SMEMSZ);
    cudaFuncSetAttribute(k_out,    cudaFuncAttributeMaxDynamicSharedMemorySize, SMEMSZ);

    k_qkv<<<dim3(96, 4), 256, SMEMSZ>>>(X, Wq, Wk, Wv);
    k_scores<<<dim3(32, 4, 32), 256, SMEMSZ>>>(cacheK);
    softmax_rows<<<Hh * Mm, 256>>>(noise, out);
    k_out<<<dim3(4, 32), 256, SMEMSZ>>>(cacheV, out);
}

// round 12
// speedup vs baseline: 1.2098x; 1.1026x over previous
#include <cuda_runtime.h>
#include <cstdint>
#include <cstddef>

// Problem constants (static in reference)
constexpr int Mm = 512, Nn = 4096, Kdim = 4096, Dd = 128, Hh = 32, Ll = 4096, Pp = 3584;
constexpr size_t OUT0 = (size_t)Mm * Nn;

// Scratch (device globals: allocation-free per harness rules)
__device__ float g_q [(size_t)Hh * Mm * Dd];   // 8 MB [H][M][D]
__device__ float g_Kn[(size_t)Hh * Mm * Dd];   // 8 MB new K rows [H][M][D]
__device__ float g_Vn[(size_t)Hh * Mm * Dd];   // 8 MB new V rows [H][M][D]
__device__ float g_S [(size_t)Hh * Mm * Ll];   // 256 MB raw scores [H*M][L]
__device__ float g_invs[Hh * Mm];              // 1/sum(exp(s)) per row

// ---------------------------------------------------------------------------
// PTX helpers (all baseline, no sm_103a-suffixed features)
// ---------------------------------------------------------------------------
__device__ __forceinline__ uint32_t smem_u32(const void* p) {
    uint32_t a;
    asm("{ .reg .u64 t; cvta.to.shared.u64 t, %1; cvt.u32.u64 %0, t; }" : "=r"(a) : "l"(p));
    return a;
}
// Cheap tf32 split: hi = truncate to 13 mantissa bits (valid tf32),
// lo = f - hi (exactly representable in tf32).
__device__ __forceinline__ void tf32split(uint32_t fraw, uint32_t& hi, uint32_t& lo) {
    hi = fraw & 0xFFFFE000u;
    lo = __float_as_uint(__uint_as_float(fraw) - __uint_as_float(hi));
}
__device__ __forceinline__ void mma8(float* c, const uint32_t* a, const uint32_t* b) {
    asm("mma.sync.aligned.m16n8k8.row.col.f32.tf32.tf32.f32 "
        "{%0,%1,%2,%3}, {%4,%5,%6,%7}, {%8,%9}, {%0,%1,%2,%3};"
        : "+f"(c[0]), "+f"(c[1]), "+f"(c[2]), "+f"(c[3])
        : "r"(a[0]), "r"(a[1]), "r"(a[2]), "r"(a[3]), "r"(b[0]), "r"(b[1]));
}
__device__ __forceinline__ void ldsm4(uint32_t& r0, uint32_t& r1, uint32_t& r2, uint32_t& r3,
                                      uint32_t addr) {
    asm volatile("ldmatrix.sync.aligned.m8n8.x4.shared.b16 {%0,%1,%2,%3}, [%4];"
                 : "=r"(r0), "=r"(r1), "=r"(r2), "=r"(r3) : "r"(addr));
}
__device__ __forceinline__ void cpasync16(uint32_t dst, const float* src) {
    asm volatile("cp.async.cg.shared.global [%0], [%1], 16;" :: "r"(dst), "l"(src));
}
#define CP_COMMIT() asm volatile("cp.async.commit_group;" ::: "memory")
#define CP_WAIT1()  asm volatile("cp.async.wait_group 1;" ::: "memory")

// ---------------------------------------------------------------------------
// SMEM: 3-stage ring. Stage = A raw f32 [128][20] + B raw (n-major [16][140]
// or K-major [128][20]). 20480 B/stage, 61440 B total.
// Row stride 20 words: LDSM 8-row wavefronts hit all 32 banks (conflict-free).
// B n-major stride 140: scalar frag bank (12*t4+g)&31, all distinct.
// ---------------------------------------------------------------------------
#define A_STR 20
#define B_STR 140
#define B_OFF_W 2560
#define STAGE_W 5120
constexpr int SMEMSZ = 3 * STAGE_W * 4;   // 61440 B

// B rows from two sources split at `split` (cache vs freshly-projected rows)
struct BSrc { const float* p0; const float* p1; int split; size_t ld; };
__device__ __forceinline__ const float* brow(const BSrc& s, int r) {
    return (r < s.split) ? s.p0 + (size_t)r * s.ld : s.p1 + (size_t)(r - s.split) * s.ld;
}

// ---- stage issue (512 threads; 1 cp.async of 16B per thread per tile) ----
__device__ __forceinline__ void issueA(uint32_t sb, const float* __restrict__ A,
                                       size_t lda, int am0, int kb, int tid) {
    int r = tid >> 2, kq = (tid & 3) * 4;
    cpasync16(sb + (r * A_STR + kq) * 4, A + (size_t)(am0 + r) * lda + kb + kq);
}
template <bool BKMAJOR>
__device__ __forceinline__ void issueB(uint32_t sb, const BSrc& bs, int bn0, int kb, int tid) {
    if (BKMAJOR) {
        int n = tid >> 2, kq = (tid & 3) * 4;
        cpasync16(sb + B_OFF_W * 4 + (n * A_STR + kq) * 4, brow(bs, bn0 + n) + kb + kq);
    } else {
        int k = tid >> 5, n0 = (tid & 31) * 4;
        cpasync16(sb + B_OFF_W * 4 + (k * B_STR + n0) * 4, brow(bs, kb + k) + bn0 + n0);
    }
}
// EXPA path: A staged via LDG -> exp -> STS (exp paid once per element)
__device__ __forceinline__ float4 ldgA(const float* __restrict__ A, size_t lda,
                                       int am0, int kb, int tid) {
    int r = tid >> 2, kq = (tid & 3) * 4;
    return *(const float4*)(A + (size_t)(am0 + r) * lda + kb + kq);
}
__device__ __forceinline__ void stsExpA(uint32_t sb, float4 v, int tid) {
    int r = tid >> 2, kq = (tid & 3) * 4;
    float ex = __expf(v.x), ey = __expf(v.y), ez = __expf(v.z), ew = __expf(v.w);
    asm volatile("st.shared.v4.f32 [%0], {%1,%2,%3,%4};"
                 :: "r"(sb + (r * A_STR + kq) * 4), "f"(ex), "f"(ey), "f"(ez), "f"(ew)
                 : "memory");
}

// ---------------------------------------------------------------------------
// GEMM core: C[128,128] = A[128xK] * B[Kx128]
// 512 threads = 16 warps, 4M x 4N; warp tile 32x32 = 2x4 m16n8k8 tiles.
// Raw fp32 smem; LDSM for A (and K-major B); mask-split in regs; 3xTF32.
// ---------------------------------------------------------------------------
template <int NCHUNK, bool BKMAJOR, bool EXPA>
__device__ __forceinline__ void gemm_tc(const float* __restrict__ A, size_t lda, int am0,
                                        BSrc bs, int bn0,
                                        uint32_t* sm, float (&acc)[2][4][4]) {
    const int tid = threadIdx.x;
    const int lane = tid & 31, wid = tid >> 5;
    const int wm0 = (wid >> 2) * 32, wn0 = (wid & 3) * 32;
    const int g = lane >> 2, t4 = lane & 3;
    const uint32_t sbase = smem_u32(sm);

#pragma unroll
    for (int i = 0; i < 2; i++)
#pragma unroll
        for (int j = 0; j < 4; j++)
#pragma unroll
            for (int q = 0; q < 4; q++) acc[i][j][q] = 0.f;

    float4 apre;
    // prolog: stages 0 and 1
    if (EXPA) {
        float4 a0 = ldgA(A, lda, am0, 0, tid);
        stsExpA(sbase, a0, tid);
        apre = ldgA(A, lda, am0, 16, tid);
    } else {
        issueA(sbase, A, lda, am0, 0, tid);
    }
    issueB<BKMAJOR>(sbase, bs, bn0, 0, tid);
    CP_COMMIT();
    if (!EXPA) issueA(sbase + STAGE_W * 4, A, lda, am0, 16, tid);
    issueB<BKMAJOR>(sbase + STAGE_W * 4, bs, bn0, 16, tid);
    CP_COMMIT();

    // per-thread constant LDSM address components
    const uint32_t a_rowbase = (wm0 + (lane & 15)) * A_STR + ((lane >> 4) << 2);
    const uint32_t b_rowbase = (wn0 + (lane & 7) + ((lane & 16) ? 8 : 0)) * A_STR +
                               ((lane & 8) ? 4 : 0);

#pragma unroll 1
    for (int c = 0; c < NCHUNK; c++) {
        CP_WAIT1();
        if (EXPA && c + 1 < NCHUNK)
            stsExpA(sbase + ((c + 1) % 3) * STAGE_W * 4, apre, tid);
        __syncthreads();
        if (c + 2 < NCHUNK) {
            uint32_t nb = sbase + ((c + 2) % 3) * STAGE_W * 4;
            if (EXPA) apre = ldgA(A, lda, am0, (c + 2) * 16, tid);
            else      issueA(nb, A, lda, am0, (c + 2) * 16, tid);
            issueB<BKMAJOR>(nb, bs, bn0, (c + 2) * 16, tid);
        }
        CP_COMMIT();

        const uint32_t aB = sbase + (c % 3) * STAGE_W * 4;
        const uint32_t bB = aB + B_OFF_W * 4;
        const uint32_t* Bs = (const uint32_t*)sm + (c % 3) * STAGE_W + B_OFF_W;

#pragma unroll
        for (int kt = 0; kt < 2; kt++) {
            // ---- A fragments (LDSM raw) + mask split ----
            uint32_t araw[2][4], ah[2][4], al[2][4];
#pragma unroll
            for (int i = 0; i < 2; i++)
                ldsm4(araw[i][0], araw[i][1], araw[i][2], araw[i][3],
                      aB + (a_rowbase + i * 16 * A_STR + kt * 8) * 4);
#pragma unroll
            for (int i = 0; i < 2; i++)
#pragma unroll
                for (int q = 0; q < 4; q++) tf32split(araw[i][q], ah[i][q], al[i][q]);
            // ---- B fragments + mask split ----
            uint32_t bh[4][2], bl[4][2];
            if (BKMAJOR) {
                uint32_t braw[4][2];
#pragma unroll
                for (int jp = 0; jp < 2; jp++) {
                    uint32_t r0, r1, r2, r3;
                    ldsm4(r0, r1, r2, r3, bB + (b_rowbase + jp * 16 * A_STR + kt * 8) * 4);
                    braw[jp * 2][0] = r0;     braw[jp * 2][1] = r1;
                    braw[jp * 2 + 1][0] = r2; braw[jp * 2 + 1][1] = r3;
                }
#pragma unroll
                for (int j = 0; j < 4; j++)
#pragma unroll
                    for (int q = 0; q < 2; q++) tf32split(braw[j][q], bh[j][q], bl[j][q]);
            } else {
                const int kc = kt * 8 + t4;
#pragma unroll
                for (int j = 0; j < 4; j++) {
                    tf32split(Bs[kc * B_STR + wn0 + j * 8 + g], bh[j][0], bl[j][0]);
                    tf32split(Bs[(kc + 4) * B_STR + wn0 + j * 8 + g], bh[j][1], bl[j][1]);
                }
            }
            // ---- MMAs, pass-major (8 independent accumulators per pass) ----
#pragma unroll
            for (int i = 0; i < 2; i++)
#pragma unroll
                for (int j = 0; j < 4; j++) mma8(acc[i][j], ah[i], bh[j]);
#pragma unroll
            for (int i = 0; i < 2; i++)
#pragma unroll
                for (int j = 0; j < 4; j++) mma8(acc[i][j], ah[i], bl[j]);
#pragma unroll
            for (int i = 0; i < 2; i++)
#pragma unroll
                for (int j = 0; j < 4; j++) mma8(acc[i][j], al[i], bh[j]);
        }
        __syncthreads();
    }
}

__device__ __forceinline__ void store_acc(float (&acc)[2][4][4], float* __restrict__ dst,
                                          size_t ldd, const float* __restrict__ rowscale) {
    const int tid = threadIdx.x;
    const int lane = tid & 31, wid = tid >> 5;
    const int wm0 = (wid >> 2) * 32, wn0 = (wid & 3) * 32;
    const int g = lane >> 2, t4 = lane & 3;
#pragma unroll
    for (int i = 0; i < 2; i++) {
        int r0 = wm0 + i * 16 + g;
        float s0 = rowscale ? rowscale[r0] : 1.f;
        float s1 = rowscale ? rowscale[r0 + 8] : 1.f;
#pragma unroll
        for (int j = 0; j < 4; j++) {
            int cn = wn0 + j * 8 + t4 * 2;
            *(float2*)&dst[(size_t)r0 * ldd + cn] =
                make_float2(acc[i][j][0] * s0, acc[i][j][1] * s0);
            *(float2*)&dst[(size_t)(r0 + 8) * ldd + cn] =
                make_float2(acc[i][j][2] * s1, acc[i][j][3] * s1);
        }
    }
}

// ---------------------------------------------------------------------------
// Kernels
// ---------------------------------------------------------------------------
extern __shared__ uint32_t dsm_u32[];

// QKV: C = X @ W_z; W is [k][n] -> B n-major
__global__ __launch_bounds__(512, 1)
void k_qkv(const float* __restrict__ X, const float* __restrict__ Wq,
           const float* __restrict__ Wk, const float* __restrict__ Wv) {
    int z = blockIdx.x >> 5, head = blockIdx.x & 31, bm0 = blockIdx.y * 128;
    const float* W = (z == 0) ? Wq : (z == 1) ? Wk : Wv;
    BSrc bs{W, W, Kdim, (size_t)Nn};
    float acc[2][4][4];
    gemm_tc<Kdim / 16, false, false>(X, Kdim, bm0, bs, head * 128, dsm_u32, acc);
    float* dst = (z == 0) ? g_q  + ((size_t)head * Mm + bm0) * Dd
               : (z == 1) ? g_Kn + ((size_t)head * Mm + bm0) * Dd
                          : g_Vn + ((size_t)head * Mm + bm0) * Dd;
    store_acc(acc, dst, Dd, nullptr);
}

// Scores: S = q @ K^T; K-cache [l][d] K-major -> LDSM both operands
__global__ __launch_bounds__(512, 1)
void k_scores(const float* __restrict__ cacheK) {
    int h = blockIdx.z, bm0 = blockIdx.y * 128, l0 = blockIdx.x * 128;
    BSrc bs{cacheK + (size_t)h * Ll * Dd, g_Kn + (size_t)h * Mm * Dd, Pp, (size_t)Dd};
    float acc[2][4][4];
    gemm_tc<Dd / 16, true, false>(g_q + (size_t)h * Mm * Dd, Dd, bm0, bs, l0, dsm_u32, acc);
    store_acc(acc, g_S + ((size_t)h * Mm + bm0) * Ll + l0, Ll, nullptr);
}

// Output: out = (exp(S) @ V) * inv_sum; exp applied once per element at stage
__global__ __launch_bounds__(512, 1)
void k_out(const float* __restrict__ cacheV, float* __restrict__ dout) {
    int h = blockIdx.y, bm0 = blockIdx.x * 128;
    BSrc bs{cacheV + (size_t)h * Ll * Dd, g_Vn + (size_t)h * Mm * Dd, Pp, (size_t)Dd};
    float acc[2][4][4];
    gemm_tc<Ll / 16, false, true>(g_S + (size_t)h * Mm * Ll, Ll, bm0, bs, 0, dsm_u32, acc);
    store_acc(acc, dout + (size_t)bm0 * Nn + h * Dd, Nn, g_invs + h * Mm + bm0);
}

// Dual-exp row kernel: reads raw S, writes normalized perturb + invs.
__global__ __launch_bounds__(256)
void softmax_rows(const float* __restrict__ noise, float* __restrict__ dout) {
    const int row = blockIdx.x;  // h*Mm + m
    const float* S = g_S + (size_t)row * Ll;
    const float* nz = noise + (size_t)row * Ll;
    float* pout = dout + OUT0 + (size_t)row * Ll;
    __shared__ float ep[Ll];
    __shared__ float r1[256], r2[256];
    const int tid = threadIdx.x;

    float ss = 0.f, sp = 0.f;
    for (int l = tid; l < Ll; l += 256) {
        float s = S[l];
        ss += __expf(s);
        float e2 = __expf((s + nz[l]) * (1.0f / 1.5f));
        ep[l] = e2;
        sp += e2;
    }
    r1[tid] = ss; r2[tid] = sp;
    __syncthreads();
    for (int st = 128; st > 0; st >>= 1) {
        if (tid < st) { r1[tid] += r1[tid + st]; r2[tid] += r2[tid + st]; }
        __syncthreads();
    }
    if (tid == 0) g_invs[row] = 1.0f / r1[0];
    const float ip = 1.0f / r2[0];
    for (int l = tid; l < Ll; l += 256) pout[l] = ep[l] * ip;
}

// ---------------------------------------------------------------------------
// Launch
// ---------------------------------------------------------------------------
extern "C" void kernel_launch(void* const* d_in, const int* in_sizes, int n_in,
                              void* d_out, int out_size) {
    const float* X      = (const float*)d_in[0];
    const float* Wq     = (const float*)d_in[1];
    const float* Wk     = (const float*)d_in[2];
    const float* Wv     = (const float*)d_in[3];
    const float* noise  = (const float*)d_in[4];
    const float* cacheK = (const float*)d_in[5];
    const float* cacheV = (const float*)d_in[6];
    float* out = (float*)d_out;
    (void)in_sizes; (void)n_in; (void)out_size;   // P is static (3584)

    cudaFuncSetAttribute(k_qkv,    cudaFuncAttributeMaxDynamicSharedMemorySize, SMEMSZ);
    cudaFuncSetAttribute(k_scores, cudaFuncAttributeMaxDynamicSharedMemorySize, SMEMSZ);
    cudaFuncSetAttribute(k_out,    cudaFuncAttributeMaxDynamicSharedMemorySize, SMEMSZ);

    k_qkv<<<dim3(96, 4), 512, SMEMSZ>>>(X, Wq, Wk, Wv);
    k_scores<<<dim3(32, 4, 32), 512, SMEMSZ>>>(cacheK);
    softmax_rows<<<Hh * Mm, 256>>>(noise, out);
    k_out<<<dim3(4, 32), 512, SMEMSZ>>>(cacheV, out);
}

// round 13
// speedup vs baseline: 1.2991x; 1.0738x over previous
#include <cuda_runtime.h>
#include <cstdint>
#include <cstddef>

// Problem constants (static in reference)
constexpr int Mm = 512, Nn = 4096, Kdim = 4096, Dd = 128, Hh = 32, Ll = 4096, Pp = 3584;
constexpr size_t OUT0 = (size_t)Mm * Nn;

// Scratch (device globals: allocation-free per harness rules)
__device__ float g_q [(size_t)Hh * Mm * Dd];   // 8 MB [H][M][D]
__device__ float g_Kn[(size_t)Hh * Mm * Dd];   // 8 MB new K rows [H][M][D]
__device__ float g_Vn[(size_t)Hh * Mm * Dd];   // 8 MB new V rows [H][M][D]
__device__ float g_S [(size_t)Hh * Mm * Ll];   // 256 MB raw scores [H*M][L]
__device__ float g_invs[Hh * Mm];              // 1/sum(exp(s)) per row

// ---------------------------------------------------------------------------
// PTX helpers (all baseline, no sm_103a-suffixed features)
// ---------------------------------------------------------------------------
__device__ __forceinline__ uint32_t smem_u32(const void* p) {
    uint32_t a;
    asm("{ .reg .u64 t; cvta.to.shared.u64 t, %1; cvt.u32.u64 %0, t; }" : "=r"(a) : "l"(p));
    return a;
}
// Cheap tf32 split: hi = truncate to 13 mantissa bits (valid tf32),
// lo = f - hi (exactly representable in tf32).
__device__ __forceinline__ void tf32split(uint32_t fraw, uint32_t& hi, uint32_t& lo) {
    hi = fraw & 0xFFFFE000u;
    lo = __float_as_uint(__uint_as_float(fraw) - __uint_as_float(hi));
}
__device__ __forceinline__ void mma8(float* c, const uint32_t* a, const uint32_t* b) {
    asm("mma.sync.aligned.m16n8k8.row.col.f32.tf32.tf32.f32 "
        "{%0,%1,%2,%3}, {%4,%5,%6,%7}, {%8,%9}, {%0,%1,%2,%3};"
        : "+f"(c[0]), "+f"(c[1]), "+f"(c[2]), "+f"(c[3])
        : "r"(a[0]), "r"(a[1]), "r"(a[2]), "r"(a[3]), "r"(b[0]), "r"(b[1]));
}
__device__ __forceinline__ void ldsm4(uint32_t& r0, uint32_t& r1, uint32_t& r2, uint32_t& r3,
                                      uint32_t addr) {
    asm volatile("ldmatrix.sync.aligned.m8n8.x4.shared.b16 {%0,%1,%2,%3}, [%4];"
                 : "=r"(r0), "=r"(r1), "=r"(r2), "=r"(r3) : "r"(addr));
}
__device__ __forceinline__ void cpasync16(uint32_t dst, const float* src) {
    asm volatile("cp.async.cg.shared.global [%0], [%1], 16;" :: "r"(dst), "l"(src));
}
#define CP_COMMIT() asm volatile("cp.async.commit_group;" ::: "memory")
#define CP_WAIT2()  asm volatile("cp.async.wait_group 2;" ::: "memory")

// ---------------------------------------------------------------------------
// SMEM: 4-stage ring, K=32 slab per stage.
//   A raw f32 [128][36]  (4608 words)
//   B raw: K-major [128][36] (4608 w) or n-major [32][140] (4480 w)
// Stage = 9216 words = 36864 B; 4 stages = 147456 B.
// A_STR=36: LDSM phase banks (4r+c)&31 distinct. B_STR=140: (12*t4+g)&31 distinct.
// ---------------------------------------------------------------------------
#define A_STR 36
#define B_STR 140
#define B_OFF_W 4608
#define STAGE_W 9216
constexpr int SMEMSZ = 4 * STAGE_W * 4;   // 147456 B

// B rows from two sources split at `split` (cache vs freshly-projected rows)
struct BSrc { const float* p0; const float* p1; int split; size_t ld; };
__device__ __forceinline__ const float* brow(const BSrc& s, int r) {
    return (r < s.split) ? s.p0 + (size_t)r * s.ld : s.p1 + (size_t)(r - s.split) * s.ld;
}

// ---- stage issue (512 threads; 2 cp.async of 16B per thread per tile) ----
__device__ __forceinline__ void issueA(uint32_t sb, const float* __restrict__ A,
                                       size_t lda, int am0, int kb, int tid) {
    int r = tid >> 2, kq = (tid & 3) * 8;
    const float* src = A + (size_t)(am0 + r) * lda + kb + kq;
    uint32_t dst = sb + (r * A_STR + kq) * 4;
    cpasync16(dst, src);
    cpasync16(dst + 16, src + 4);
}
template <bool BKMAJOR>
__device__ __forceinline__ void issueB(uint32_t sb, const BSrc& bs, int bn0, int kb, int tid) {
    if (BKMAJOR) {
        int n = tid >> 2, kq = (tid & 3) * 8;
        const float* src = brow(bs, bn0 + n) + kb + kq;
        uint32_t dst = sb + B_OFF_W * 4 + (n * A_STR + kq) * 4;
        cpasync16(dst, src);
        cpasync16(dst + 16, src + 4);
    } else {
        int k = tid >> 4, n0 = (tid & 15) * 8;
        const float* src = brow(bs, kb + k) + bn0 + n0;
        uint32_t dst = sb + B_OFF_W * 4 + (k * B_STR + n0) * 4;
        cpasync16(dst, src);
        cpasync16(dst + 16, src + 4);
    }
}
// EXPA path: A staged via LDG -> exp -> STS (exp paid once per element)
struct F4x2 { float4 a, b; };
__device__ __forceinline__ F4x2 ldgA(const float* __restrict__ A, size_t lda,
                                     int am0, int kb, int tid) {
    int r = tid >> 2, kq = (tid & 3) * 8;
    const float* p = A + (size_t)(am0 + r) * lda + kb + kq;
    F4x2 v;
    v.a = *(const float4*)p;
    v.b = *(const float4*)(p + 4);
    return v;
}
__device__ __forceinline__ void stsExpA(uint32_t sb, F4x2 v, int tid) {
    int r = tid >> 2, kq = (tid & 3) * 8;
    uint32_t d0 = sb + (r * A_STR + kq) * 4;
    float e0 = __expf(v.a.x), e1 = __expf(v.a.y), e2 = __expf(v.a.z), e3 = __expf(v.a.w);
    float e4 = __expf(v.b.x), e5 = __expf(v.b.y), e6 = __expf(v.b.z), e7 = __expf(v.b.w);
    asm volatile("st.shared.v4.f32 [%0], {%1,%2,%3,%4};"
                 :: "r"(d0), "f"(e0), "f"(e1), "f"(e2), "f"(e3) : "memory");
    asm volatile("st.shared.v4.f32 [%0], {%1,%2,%3,%4};"
                 :: "r"(d0 + 16), "f"(e4), "f"(e5), "f"(e6), "f"(e7) : "memory");
}

// ---------------------------------------------------------------------------
// GEMM core: C[128,128] = A[128xK] * B[Kx128]
// 512 threads = 16 warps, 4M x 4N; warp tile 32x32 = 2x4 m16n8k8 tiles.
// Raw fp32 smem; LDSM for A (and K-major B); mask-split in regs; 3xTF32.
// K=32 per barrier (4 kt sub-steps).
// ---------------------------------------------------------------------------
template <int NCHUNK, bool BKMAJOR, bool EXPA>
__device__ __forceinline__ void gemm_tc(const float* __restrict__ A, size_t lda, int am0,
                                        BSrc bs, int bn0,
                                        uint32_t* sm, float (&acc)[2][4][4]) {
    const int tid = threadIdx.x;
    const int lane = tid & 31, wid = tid >> 5;
    const int wm0 = (wid >> 2) * 32, wn0 = (wid & 3) * 32;
    const int g = lane >> 2, t4 = lane & 3;
    const uint32_t sbase = smem_u32(sm);

#pragma unroll
    for (int i = 0; i < 2; i++)
#pragma unroll
        for (int j = 0; j < 4; j++)
#pragma unroll
            for (int q = 0; q < 4; q++) acc[i][j][q] = 0.f;

    F4x2 apre;
    // prolog: stages 0,1,2
    if (EXPA) {
        F4x2 a0 = ldgA(A, lda, am0, 0, tid);
        stsExpA(sbase, a0, tid);
        apre = ldgA(A, lda, am0, 32, tid);
    } else {
        issueA(sbase, A, lda, am0, 0, tid);
    }
    issueB<BKMAJOR>(sbase, bs, bn0, 0, tid);
    CP_COMMIT();
    if (!EXPA) issueA(sbase + STAGE_W * 4, A, lda, am0, 32, tid);
    issueB<BKMAJOR>(sbase + STAGE_W * 4, bs, bn0, 32, tid);
    CP_COMMIT();
    if (!EXPA) issueA(sbase + 2 * STAGE_W * 4, A, lda, am0, 64, tid);
    issueB<BKMAJOR>(sbase + 2 * STAGE_W * 4, bs, bn0, 64, tid);
    CP_COMMIT();

    // per-thread constant LDSM address components
    const uint32_t a_rowbase = (wm0 + (lane & 15)) * A_STR + ((lane >> 4) << 2);
    const uint32_t b_rowbase = (wn0 + (lane & 7) + ((lane & 16) ? 8 : 0)) * A_STR +
                               ((lane & 8) ? 4 : 0);

#pragma unroll 1
    for (int c = 0; c < NCHUNK; c++) {
        CP_WAIT2();
        if (EXPA && c + 1 < NCHUNK)
            stsExpA(sbase + ((c + 1) & 3) * STAGE_W * 4, apre, tid);
        __syncthreads();
        if (c + 3 < NCHUNK) {
            uint32_t nb = sbase + ((c + 3) & 3) * STAGE_W * 4;
            if (!EXPA) issueA(nb, A, lda, am0, (c + 3) * 32, tid);
            issueB<BKMAJOR>(nb, bs, bn0, (c + 3) * 32, tid);
        }
        if (EXPA && c + 2 < NCHUNK) apre = ldgA(A, lda, am0, (c + 2) * 32, tid);
        CP_COMMIT();

        const uint32_t aB = sbase + (c & 3) * STAGE_W * 4;
        const uint32_t bB = aB + B_OFF_W * 4;
        const uint32_t* Bs = (const uint32_t*)sm + (c & 3) * STAGE_W + B_OFF_W;

#pragma unroll
        for (int kt = 0; kt < 4; kt++) {
            // ---- A fragments (LDSM raw) + mask split ----
            uint32_t araw[2][4], ah[2][4], al[2][4];
#pragma unroll
            for (int i = 0; i < 2; i++)
                ldsm4(araw[i][0], araw[i][1], araw[i][2], araw[i][3],
                      aB + (a_rowbase + i * 16 * A_STR + kt * 8) * 4);
#pragma unroll
            for (int i = 0; i < 2; i++)
#pragma unroll
                for (int q = 0; q < 4; q++) tf32split(araw[i][q], ah[i][q], al[i][q]);
            // ---- B fragments + mask split ----
            uint32_t bh[4][2], bl[4][2];
            if (BKMAJOR) {
                uint32_t braw[4][2];
#pragma unroll
                for (int jp = 0; jp < 2; jp++) {
                    uint32_t r0, r1, r2, r3;
                    ldsm4(r0, r1, r2, r3, bB + (b_rowbase + jp * 16 * A_STR + kt * 8) * 4);
                    braw[jp * 2][0] = r0;     braw[jp * 2][1] = r1;
                    braw[jp * 2 + 1][0] = r2; braw[jp * 2 + 1][1] = r3;
                }
#pragma unroll
                for (int j = 0; j < 4; j++)
#pragma unroll
                    for (int q = 0; q < 2; q++) tf32split(braw[j][q], bh[j][q], bl[j][q]);
            } else {
                const int kc = kt * 8 + t4;
#pragma unroll
                for (int j = 0; j < 4; j++) {
                    tf32split(Bs[kc * B_STR + wn0 + j * 8 + g], bh[j][0], bl[j][0]);
                    tf32split(Bs[(kc + 4) * B_STR + wn0 + j * 8 + g], bh[j][1], bl[j][1]);
                }
            }
            // ---- MMAs, pass-major (8 independent accumulators per pass) ----
#pragma unroll
            for (int i = 0; i < 2; i++)
#pragma unroll
                for (int j = 0; j < 4; j++) mma8(acc[i][j], ah[i], bh[j]);
#pragma unroll
            for (int i = 0; i < 2; i++)
#pragma unroll
                for (int j = 0; j < 4; j++) mma8(acc[i][j], ah[i], bl[j]);
#pragma unroll
            for (int i = 0; i < 2; i++)
#pragma unroll
                for (int j = 0; j < 4; j++) mma8(acc[i][j], al[i], bh[j]);
        }
        __syncthreads();
    }
}

__device__ __forceinline__ void store_acc(float (&acc)[2][4][4], float* __restrict__ dst,
                                          size_t ldd, const float* __restrict__ rowscale) {
    const int tid = threadIdx.x;
    const int lane = tid & 31, wid = tid >> 5;
    const int wm0 = (wid >> 2) * 32, wn0 = (wid & 3) * 32;
    const int g = lane >> 2, t4 = lane & 3;
#pragma unroll
    for (int i = 0; i < 2; i++) {
        int r0 = wm0 + i * 16 + g;
        float s0 = rowscale ? rowscale[r0] : 1.f;
        float s1 = rowscale ? rowscale[r0 + 8] : 1.f;
#pragma unroll
        for (int j = 0; j < 4; j++) {
            int cn = wn0 + j * 8 + t4 * 2;
            *(float2*)&dst[(size_t)r0 * ldd + cn] =
                make_float2(acc[i][j][0] * s0, acc[i][j][1] * s0);
            *(float2*)&dst[(size_t)(r0 + 8) * ldd + cn] =
                make_float2(acc[i][j][2] * s1, acc[i][j][3] * s1);
        }
    }
}

// ---------------------------------------------------------------------------
// Kernels
// ---------------------------------------------------------------------------
extern __shared__ uint32_t dsm_u32[];

// QKV: C = X @ W_z; W is [k][n] -> B n-major
__global__ __launch_bounds__(512, 1)
void k_qkv(const float* __restrict__ X, const float* __restrict__ Wq,
           const float* __restrict__ Wk, const float* __restrict__ Wv) {
    int z = blockIdx.x >> 5, head = blockIdx.x & 31, bm0 = blockIdx.y * 128;
    const float* W = (z == 0) ? Wq : (z == 1) ? Wk : Wv;
    BSrc bs{W, W, Kdim, (size_t)Nn};
    float acc[2][4][4];
    gemm_tc<Kdim / 32, false, false>(X, Kdim, bm0, bs, head * 128, dsm_u32, acc);
    float* dst = (z == 0) ? g_q  + ((size_t)head * Mm + bm0) * Dd
               : (z == 1) ? g_Kn + ((size_t)head * Mm + bm0) * Dd
                          : g_Vn + ((size_t)head * Mm + bm0) * Dd;
    store_acc(acc, dst, Dd, nullptr);
}

// Scores: S = q @ K^T; K-cache [l][d] K-major -> LDSM both operands
__global__ __launch_bounds__(512, 1)
void k_scores(const float* __restrict__ cacheK) {
    int h = blockIdx.z, bm0 = blockIdx.y * 128, l0 = blockIdx.x * 128;
    BSrc bs{cacheK + (size_t)h * Ll * Dd, g_Kn + (size_t)h * Mm * Dd, Pp, (size_t)Dd};
    float acc[2][4][4];
    gemm_tc<Dd / 32, true, false>(g_q + (size_t)h * Mm * Dd, Dd, bm0, bs, l0, dsm_u32, acc);
    store_acc(acc, g_S + ((size_t)h * Mm + bm0) * Ll + l0, Ll, nullptr);
}

// Output: out = (exp(S) @ V) * inv_sum; exp applied once per element at stage
__global__ __launch_bounds__(512, 1)
void k_out(const float* __restrict__ cacheV, float* __restrict__ dout) {
    int h = blockIdx.y, bm0 = blockIdx.x * 128;
    BSrc bs{cacheV + (size_t)h * Ll * Dd, g_Vn + (size_t)h * Mm * Dd, Pp, (size_t)Dd};
    float acc[2][4][4];
    gemm_tc<Ll / 32, false, true>(g_S + (size_t)h * Mm * Ll, Ll, bm0, bs, 0, dsm_u32, acc);
    store_acc(acc, dout + (size_t)bm0 * Nn + h * Dd, Nn, g_invs + h * Mm + bm0);
}

// Dual-exp row kernel: reads raw S, writes normalized perturb + invs.
__global__ __launch_bounds__(256)
void softmax_rows(const float* __restrict__ noise, float* __restrict__ dout) {
    const int row = blockIdx.x;  // h*Mm + m
    const float* S = g_S + (size_t)row * Ll;
    const float* nz = noise + (size_t)row * Ll;
    float* pout = dout + OUT0 + (size_t)row * Ll;
    __shared__ float ep[Ll];
    __shared__ float r1[256], r2[256];
    const int tid = threadIdx.x;

    float ss = 0.f, sp = 0.f;
    for (int l = tid; l < Ll; l += 256) {
        float s = S[l];
        ss += __expf(s);
        float e2 = __expf((s + nz[l]) * (1.0f / 1.5f));
        ep[l] = e2;
        sp += e2;
    }
    r1[tid] = ss; r2[tid] = sp;
    __syncthreads();
    for (int st = 128; st > 0; st >>= 1) {
        if (tid < st) { r1[tid] += r1[tid + st]; r2[tid] += r2[tid + st]; }
        __syncthreads();
    }
    if (tid == 0) g_invs[row] = 1.0f / r1[0];
    const float ip = 1.0f / r2[0];
    for (int l = tid; l < Ll; l += 256) pout[l] = ep[l] * ip;
}

// ---------------------------------------------------------------------------
// Launch
// ---------------------------------------------------------------------------
extern "C" void kernel_launch(void* const* d_in, const int* in_sizes, int n_in,
                              void* d_out, int out_size) {
    const float* X      = (const float*)d_in[0];
    const float* Wq     = (const float*)d_in[1];
    const float* Wk     = (const float*)d_in[2];
    const float* Wv     = (const float*)d_in[3];
    const float* noise  = (const float*)d_in[4];
    const float* cacheK = (const float*)d_in[5];
    const float* cacheV = (const float*)d_in[6];
    float* out = (float*)d_out;
    (void)in_sizes; (void)n_in; (void)out_size;   // P is static (3584)

    cudaFuncSetAttribute(k_qkv,    cudaFuncAttributeMaxDynamicSharedMemorySize, SMEMSZ);
    cudaFuncSetAttribute(k_scores, cudaFuncAttributeMaxDynamicSharedMemorySize, SMEMSZ);
    cudaFuncSetAttribute(k_out,    cudaFuncAttributeMaxDynamicSharedMemorySize, SMEMSZ);

    k_qkv<<<dim3(96, 4), 512, SMEMSZ>>>(X, Wq, Wk, Wv);
    k_scores<<<dim3(32, 4, 32), 512, SMEMSZ>>>(cacheK);
    softmax_rows<<<Hh * Mm, 256>>>(noise, out);
    k_out<<<dim3(4, 32), 512, SMEMSZ>>>(cacheV, out);
}